// round 1
// baseline (speedup 1.0000x reference)
#include <cuda_runtime.h>
#include <math.h>

// Problem constants
#define T_   2048
#define E_   16
#define H_   2048
#define I_   1408
#define K_   4
#define A_TOT (T_ * K_)   // 8192 assignments

// GEMM tiling
#define BM 128
#define BN 64
#define BK 16

// ---------------- Device scratch (no allocations allowed) ----------------
__device__ int   d_topk_idx[A_TOT];
__device__ float d_topk_w[A_TOT];
__device__ int   d_tok[A_TOT];     // token per sorted assignment
__device__ float d_wt[A_TOT];      // routing weight per sorted assignment
__device__ int   d_pos[A_TOT];     // sorted position of assignment (t,k)
__device__ int   d_off[E_ + 1];    // per-expert segment offsets
__device__ float d_hbuf[(size_t)A_TOT * I_];  // silu(gate)*up per assignment
__device__ float d_obuf[(size_t)A_TOT * H_];  // per-assignment down output (weighted)

// ---------------- 1. Router: softmax -> top4 -> renormalize ----------------
__global__ void router_kernel(const float* __restrict__ logits) {
    int t = blockIdx.x * blockDim.x + threadIdx.x;
    if (t >= T_) return;
    float l[E_];
#pragma unroll
    for (int e = 0; e < E_; e++) l[e] = logits[t * E_ + e];

    unsigned used = 0u;
    float val[K_]; int idx[K_];
#pragma unroll
    for (int k = 0; k < K_; k++) {
        float bv = -INFINITY; int bi = 0;
#pragma unroll
        for (int e = 0; e < E_; e++) {
            bool ok = !((used >> e) & 1u) && (l[e] > bv);
            bv = ok ? l[e] : bv;
            bi = ok ? e : bi;
        }
        used |= (1u << bi);
        val[k] = bv; idx[k] = bi;
    }
    // renormalized top-k probs == softmax over the selected logits
    float m = val[0];
    float s = 0.f;
#pragma unroll
    for (int k = 0; k < K_; k++) { val[k] = __expf(val[k] - m); s += val[k]; }
    float inv = 1.f / s;
#pragma unroll
    for (int k = 0; k < K_; k++) {
        d_topk_idx[t * K_ + k] = idx[k];
        d_topk_w[t * K_ + k]   = val[k] * inv;
    }
}

// ---------------- 2. Deterministic counting sort by expert ----------------
// 256 threads = 16 experts x 16 chunks; stable, atomic-free.
__global__ void sort_kernel() {
    __shared__ int sidx[A_TOT];   // 32 KB
    __shared__ int scnt[256];
    __shared__ int sbase[256];
    int tid = threadIdx.x;
    for (int a = tid; a < A_TOT; a += 256) sidx[a] = d_topk_idx[a];
    __syncthreads();

    const int CH = A_TOT / 16;    // 512
    int e = tid >> 4;
    int c = tid & 15;
    int cn = 0;
    for (int a = c * CH; a < (c + 1) * CH; a++) cn += (sidx[a] == e);
    scnt[tid] = cn;
    __syncthreads();

    if (tid == 0) {
        int run = 0;
        for (int ee = 0; ee < E_; ee++) {
            d_off[ee] = run;
            for (int cc = 0; cc < 16; cc++) { sbase[ee * 16 + cc] = run; run += scnt[ee * 16 + cc]; }
        }
        d_off[E_] = run;   // == A_TOT
    }
    __syncthreads();

    int p = sbase[tid];
    for (int a = c * CH; a < (c + 1) * CH; a++) {
        if (sidx[a] == e) {
            d_tok[p] = a >> 2;           // a / K_
            d_wt[p]  = d_topk_w[a];
            d_pos[a] = p;
            p++;
        }
    }
}

// ---------------- 3. Fused gate+up GEMM with SiLU epilogue ----------------
// Per expert e: Hbuf[m, i] = silu(X[m,:] . Gw[i,:]) * (X[m,:] . Uw[i,:])
// Both operands K-major (contiguous over H) -> NT GEMM.
__global__ __launch_bounds__(256, 2)
void gemm_gateup(const float* __restrict__ x,
                 const float* __restrict__ gate_w,
                 const float* __restrict__ up_w) {
    int e = blockIdx.z;
    int base = d_off[e];
    int n_e = d_off[e + 1] - base;
    int m0 = blockIdx.y * BM;
    if (m0 >= n_e) return;
    int n0 = blockIdx.x * BN;

    __shared__ float As[BK][BM];
    __shared__ float Bg[BK][BN];
    __shared__ float Bu[BK][BN];

    int tid = threadIdx.x;
    int ty = tid >> 4;     // 0..15 -> rows ty*8..+7
    int tx = tid & 15;     // 0..15 -> cols tx*4..+3

    // Pre-resolve tokens for the 2 A-rows this thread loads each tile
    int tok[2];
#pragma unroll
    for (int lp = 0; lp < 2; lp++) {
        int row = (tid + lp * 256) >> 2;
        int m = m0 + row;
        tok[lp] = (m < n_e) ? d_tok[base + m] : -1;
    }

    const float* gw = gate_w + (size_t)e * I_ * H_;
    const float* uw = up_w   + (size_t)e * I_ * H_;

    float accg[8][4], accu[8][4];
#pragma unroll
    for (int i = 0; i < 8; i++)
#pragma unroll
        for (int j = 0; j < 4; j++) { accg[i][j] = 0.f; accu[i][j] = 0.f; }

    for (int k0 = 0; k0 < H_; k0 += BK) {
#pragma unroll
        for (int lp = 0; lp < 2; lp++) {
            int idx = tid + lp * 256;
            int row = idx >> 2;
            int c4 = (idx & 3) << 2;
            float4 v = make_float4(0.f, 0.f, 0.f, 0.f);
            if (tok[lp] >= 0)
                v = *(const float4*)&x[(size_t)tok[lp] * H_ + k0 + c4];
            As[c4 + 0][row] = v.x; As[c4 + 1][row] = v.y;
            As[c4 + 2][row] = v.z; As[c4 + 3][row] = v.w;
        }
        {
            int row = tid >> 2;          // 0..63
            int c4 = (tid & 3) << 2;
            size_t off = (size_t)(n0 + row) * H_ + k0 + c4;
            float4 g4 = *(const float4*)&gw[off];
            Bg[c4 + 0][row] = g4.x; Bg[c4 + 1][row] = g4.y;
            Bg[c4 + 2][row] = g4.z; Bg[c4 + 3][row] = g4.w;
            float4 u4 = *(const float4*)&uw[off];
            Bu[c4 + 0][row] = u4.x; Bu[c4 + 1][row] = u4.y;
            Bu[c4 + 2][row] = u4.z; Bu[c4 + 3][row] = u4.w;
        }
        __syncthreads();
#pragma unroll
        for (int kk = 0; kk < BK; kk++) {
            float a[8], bg[4], bu[4];
#pragma unroll
            for (int i = 0; i < 8; i++) a[i] = As[kk][ty * 8 + i];
#pragma unroll
            for (int j = 0; j < 4; j++) { bg[j] = Bg[kk][tx * 4 + j]; bu[j] = Bu[kk][tx * 4 + j]; }
#pragma unroll
            for (int i = 0; i < 8; i++)
#pragma unroll
                for (int j = 0; j < 4; j++) {
                    accg[i][j] += a[i] * bg[j];
                    accu[i][j] += a[i] * bu[j];
                }
        }
        __syncthreads();
    }

#pragma unroll
    for (int i = 0; i < 8; i++) {
        int m = m0 + ty * 8 + i;
        if (m < n_e) {
            float r[4];
#pragma unroll
            for (int j = 0; j < 4; j++) {
                float g = accg[i][j];
                float s = g * (1.f / (1.f + __expf(-g)));   // silu
                r[j] = s * accu[i][j];
            }
            *(float4*)&d_hbuf[(size_t)(base + m) * I_ + n0 + tx * 4] =
                make_float4(r[0], r[1], r[2], r[3]);
        }
    }
}

// ---------------- 4. Down projection GEMM, weighted ----------------
// obuf[m, h] = wt[m] * ( Hbuf[m,:] . Dw[h,:] )   (Dw rows contiguous over I)
__global__ __launch_bounds__(256, 2)
void gemm_down(const float* __restrict__ down_w) {
    int e = blockIdx.z;
    int base = d_off[e];
    int n_e = d_off[e + 1] - base;
    int m0 = blockIdx.y * BM;
    if (m0 >= n_e) return;
    int n0 = blockIdx.x * BN;   // over H

    __shared__ float As[BK][BM];
    __shared__ float Bs[BK][BN];

    int tid = threadIdx.x;
    int ty = tid >> 4;
    int tx = tid & 15;

    const float* dw = down_w + (size_t)e * H_ * I_;

    float acc[8][4];
#pragma unroll
    for (int i = 0; i < 8; i++)
#pragma unroll
        for (int j = 0; j < 4; j++) acc[i][j] = 0.f;

    for (int k0 = 0; k0 < I_; k0 += BK) {
#pragma unroll
        for (int lp = 0; lp < 2; lp++) {
            int idx = tid + lp * 256;
            int row = idx >> 2;
            int c4 = (idx & 3) << 2;
            int m = m0 + row;
            float4 v = make_float4(0.f, 0.f, 0.f, 0.f);
            if (m < n_e)
                v = *(const float4*)&d_hbuf[(size_t)(base + m) * I_ + k0 + c4];
            As[c4 + 0][row] = v.x; As[c4 + 1][row] = v.y;
            As[c4 + 2][row] = v.z; As[c4 + 3][row] = v.w;
        }
        {
            int row = tid >> 2;
            int c4 = (tid & 3) << 2;
            float4 v = *(const float4*)&dw[(size_t)(n0 + row) * I_ + k0 + c4];
            Bs[c4 + 0][row] = v.x; Bs[c4 + 1][row] = v.y;
            Bs[c4 + 2][row] = v.z; Bs[c4 + 3][row] = v.w;
        }
        __syncthreads();
#pragma unroll
        for (int kk = 0; kk < BK; kk++) {
            float a[8], b[4];
#pragma unroll
            for (int i = 0; i < 8; i++) a[i] = As[kk][ty * 8 + i];
#pragma unroll
            for (int j = 0; j < 4; j++) b[j] = Bs[kk][tx * 4 + j];
#pragma unroll
            for (int i = 0; i < 8; i++)
#pragma unroll
                for (int j = 0; j < 4; j++) acc[i][j] += a[i] * b[j];
        }
        __syncthreads();
    }

#pragma unroll
    for (int i = 0; i < 8; i++) {
        int m = m0 + ty * 8 + i;
        if (m < n_e) {
            float w = d_wt[base + m];
            *(float4*)&d_obuf[(size_t)(base + m) * H_ + n0 + tx * 4] =
                make_float4(w * acc[i][0], w * acc[i][1], w * acc[i][2], w * acc[i][3]);
        }
    }
}

// ---------------- 5. Combine per-token contributions ----------------
__global__ void combine_kernel(float* __restrict__ out) {
    int gid = blockIdx.x * blockDim.x + threadIdx.x;   // over T*H/4
    int t = gid / (H_ / 4);
    int h4 = (gid - t * (H_ / 4)) * 4;
    float4 s = make_float4(0.f, 0.f, 0.f, 0.f);
#pragma unroll
    for (int k = 0; k < K_; k++) {
        int p = d_pos[t * K_ + k];
        float4 v = *(const float4*)&d_obuf[(size_t)p * H_ + h4];
        s.x += v.x; s.y += v.y; s.z += v.z; s.w += v.w;
    }
    *(float4*)&out[(size_t)t * H_ + h4] = s;
}

// ---------------- Launch ----------------
extern "C" void kernel_launch(void* const* d_in, const int* in_sizes, int n_in,
                              void* d_out, int out_size) {
    const float* x      = (const float*)d_in[0];
    const float* logits = (const float*)d_in[1];
    const float* gate_w = (const float*)d_in[2];
    const float* up_w   = (const float*)d_in[3];
    const float* down_w = (const float*)d_in[4];
    float* out = (float*)d_out;

    router_kernel<<<T_ / 256, 256>>>(logits);
    sort_kernel<<<1, 256>>>();

    dim3 g1(I_ / BN, T_ / BM, E_);   // 22 x 16 x 16
    gemm_gateup<<<g1, 256>>>(x, gate_w, up_w);

    dim3 g2(H_ / BN, T_ / BM, E_);   // 32 x 16 x 16
    gemm_down<<<g2, 256>>>(down_w);

    combine_kernel<<<(T_ * H_ / 4) / 256, 256>>>(out);
}

// round 3
// speedup vs baseline: 3.2087x; 3.2087x over previous
#include <cuda_runtime.h>
#include <math.h>
#include <stdint.h>

// Problem constants
#define T_   2048
#define E_   16
#define H_   2048
#define I_   1408
#define K_   4
#define A_TOT (T_ * K_)   // 8192 assignments

// GEMM tiling (tf32 mma.sync)
#define BM 128
#define BN 128
#define BK 32
#define STAGES 3
#define SFLT 8192                       // floats per stage: A 4096 + B 4096
#define GEMM_SMEM (STAGES * SFLT * 4)   // 98304 bytes

// ---------------- Device scratch ----------------
__device__ int   d_topk_idx[A_TOT];
__device__ float d_topk_w[A_TOT];
__device__ int   d_tok[A_TOT];
__device__ float d_wt[A_TOT];
__device__ int   d_pos[A_TOT];
__device__ int   d_off[E_ + 1];
__device__ float d_xs[(size_t)A_TOT * H_];    // gathered + tf32-rounded x
__device__ float d_g[(size_t)A_TOT * I_];     // gate raw
__device__ float d_u[(size_t)A_TOT * I_];     // up raw
__device__ float d_hbuf[(size_t)A_TOT * I_];  // silu(g)*u, tf32-rounded
__device__ float d_obuf[(size_t)A_TOT * H_];  // weighted down outputs

// ---------------- helpers ----------------
__device__ __forceinline__ uint32_t smem_u32(const void* p) {
    uint32_t a;
    asm("{ .reg .u64 t; cvta.to.shared.u64 t, %1; cvt.u32.u64 %0, t; }" : "=r"(a) : "l"(p));
    return a;
}
__device__ __forceinline__ float rna_tf32(float v) {
    uint32_t r;
    asm("cvt.rna.tf32.f32 %0, %1;" : "=r"(r) : "f"(v));
    return __uint_as_float(r);
}
__device__ __forceinline__ uint32_t rna_tf32_u(float v) {
    uint32_t r;
    asm("cvt.rna.tf32.f32 %0, %1;" : "=r"(r) : "f"(v));
    return r;
}

#define MMA_TF32(c, a, b) \
    asm volatile("mma.sync.aligned.m16n8k8.row.col.f32.tf32.tf32.f32 " \
        "{%0,%1,%2,%3}, {%4,%5,%6,%7}, {%8,%9}, {%0,%1,%2,%3};" \
        : "+f"((c)[0]), "+f"((c)[1]), "+f"((c)[2]), "+f"((c)[3]) \
        : "r"((a)[0]), "r"((a)[1]), "r"((a)[2]), "r"((a)[3]), "r"((b)[0]), "r"((b)[1]))

// ---------------- 1. Router ----------------
__global__ void router_kernel(const float* __restrict__ logits) {
    int t = blockIdx.x * blockDim.x + threadIdx.x;
    if (t >= T_) return;
    float l[E_];
#pragma unroll
    for (int e = 0; e < E_; e++) l[e] = logits[t * E_ + e];
    unsigned used = 0u;
    float val[K_]; int idx[K_];
#pragma unroll
    for (int k = 0; k < K_; k++) {
        float bv = -INFINITY; int bi = 0;
#pragma unroll
        for (int e = 0; e < E_; e++) {
            bool ok = !((used >> e) & 1u) && (l[e] > bv);
            bv = ok ? l[e] : bv;
            bi = ok ? e : bi;
        }
        used |= (1u << bi);
        val[k] = bv; idx[k] = bi;
    }
    float m = val[0], s = 0.f;
#pragma unroll
    for (int k = 0; k < K_; k++) { val[k] = __expf(val[k] - m); s += val[k]; }
    float inv = 1.f / s;
#pragma unroll
    for (int k = 0; k < K_; k++) {
        d_topk_idx[t * K_ + k] = idx[k];
        d_topk_w[t * K_ + k]   = val[k] * inv;
    }
}

// ---------------- 2. Deterministic counting sort ----------------
__global__ void sort_kernel() {
    __shared__ int sidx[A_TOT];
    __shared__ int scnt[256];
    __shared__ int sbase[256];
    int tid = threadIdx.x;
    for (int a = tid; a < A_TOT; a += 256) sidx[a] = d_topk_idx[a];
    __syncthreads();
    const int CH = A_TOT / 16;
    int e = tid >> 4, c = tid & 15, cn = 0;
    for (int a = c * CH; a < (c + 1) * CH; a++) cn += (sidx[a] == e);
    scnt[tid] = cn;
    __syncthreads();
    if (tid == 0) {
        int run = 0;
        for (int ee = 0; ee < E_; ee++) {
            d_off[ee] = run;
            for (int cc = 0; cc < 16; cc++) { sbase[ee * 16 + cc] = run; run += scnt[ee * 16 + cc]; }
        }
        d_off[E_] = run;
    }
    __syncthreads();
    int p = sbase[tid];
    for (int a = c * CH; a < (c + 1) * CH; a++) {
        if (sidx[a] == e) {
            d_tok[p] = a >> 2;
            d_wt[p]  = d_topk_w[a];
            d_pos[a] = p;
            p++;
        }
    }
}

// ---------------- 3. Gather x rows (tf32 rounding) ----------------
__global__ void gather_kernel(const float* __restrict__ x) {
    int p = blockIdx.x;
    int tok = d_tok[p];
    const float4* src = (const float4*)(x + (size_t)tok * H_);
    float4* dst = (float4*)(d_xs + (size_t)p * H_);
    for (int i = threadIdx.x; i < H_ / 4; i += 256) {
        float4 v = src[i];
        v.x = rna_tf32(v.x); v.y = rna_tf32(v.y);
        v.z = rna_tf32(v.z); v.w = rna_tf32(v.w);
        dst[i] = v;
    }
}

// ---------------- 4. Grouped GEMM (tf32 mma.sync) ----------------
// C[base+m, n] = (wt?) * sum_k A[base+m, k] * B[e, n, k]
// A rows gathered contiguous per expert (pre-rounded tf32). B rounded in-register.
#define ISSUE_STAGE(kt, st) do {                                                  \
    if ((kt) < NT) {                                                              \
        int k0 = (kt) * BK;                                                       \
        uint32_t sa = smbase + (st) * (SFLT * 4);                                 \
        uint32_t sbb = sa + 4096 * 4;                                             \
        _Pragma("unroll")                                                         \
        for (int i = 0; i < 4; i++) {                                             \
            int r = lr + 32 * i;                                                  \
            uint32_t sw = (uint32_t)((r * 32 + ((lj ^ (r & 7)) << 2)) * 4);       \
            const float* srca = A + (size_t)(base + m0 + r) * Kdim + k0 + lj * 4; \
            int vs = (m0 + r < n_e) ? 16 : 0;                                     \
            asm volatile("cp.async.cg.shared.global [%0], [%1], 16, %2;"          \
                         :: "r"(sa + sw), "l"(srca), "r"(vs) : "memory");         \
            const float* srcb = Bexp + (size_t)(n0 + r) * Kdim + k0 + lj * 4;     \
            asm volatile("cp.async.cg.shared.global [%0], [%1], 16;"              \
                         :: "r"(sbb + sw), "l"(srcb) : "memory");                 \
        }                                                                         \
    }                                                                             \
    asm volatile("cp.async.commit_group;" ::: "memory");                          \
} while (0)

__global__ __launch_bounds__(256)
void gemm_tc(const float* __restrict__ A, const float* __restrict__ Bw,
             float* __restrict__ C, int Kdim, int N, int use_wt) {
    int e = blockIdx.z;
    int base = d_off[e];
    int n_e  = d_off[e + 1] - base;
    int m0 = blockIdx.y * BM;
    if (m0 >= n_e) return;
    int n0 = blockIdx.x * BN;

    extern __shared__ float sm[];
    uint32_t smbase = smem_u32(sm);
    int tid = threadIdx.x;
    int wid = tid >> 5, lane = tid & 31;
    int q = lane >> 2, tig = lane & 3;
    int lr = tid >> 3, lj = tid & 7;          // cp.async: row-of-32, 16B chunk

    const float* Bexp = Bw + (size_t)e * N * Kdim;
    int NT = Kdim / BK;

    ISSUE_STAGE(0, 0);
    ISSUE_STAGE(1, 1);

    int wm = (wid & 1) << 6;    // warp M band (0/64)
    int wn = (wid >> 1) << 5;   // warp N band (0/32/64/96)

    float acc[4][4][4];
#pragma unroll
    for (int mt = 0; mt < 4; mt++)
#pragma unroll
        for (int nt = 0; nt < 4; nt++)
#pragma unroll
            for (int r = 0; r < 4; r++) acc[mt][nt][r] = 0.f;

    int rowAoff[4], rowBoff[4];
#pragma unroll
    for (int mt = 0; mt < 4; mt++) rowAoff[mt] = (wm + mt * 16 + q) * 32 + tig;
#pragma unroll
    for (int nt = 0; nt < 4; nt++) rowBoff[nt] = (wn + nt * 8 + q) * 32 + tig;

    for (int kt = 0; kt < NT; kt++) {
        asm volatile("cp.async.wait_group 1;" ::: "memory");
        __syncthreads();
        ISSUE_STAGE(kt + 2, (kt + 2) % STAGES);
        const float* As = sm + (kt % STAGES) * SFLT;
        const float* Bs = As + 4096;
#pragma unroll
        for (int kk = 0; kk < 4; kk++) {
            int x0 = ((2 * kk) ^ q) << 2;
            uint32_t a[4][4];
#pragma unroll
            for (int mt = 0; mt < 4; mt++) {
                a[mt][0] = __float_as_uint(As[rowAoff[mt] + x0]);
                a[mt][1] = __float_as_uint(As[rowAoff[mt] + 256 + x0]);
                a[mt][2] = __float_as_uint(As[rowAoff[mt] + (x0 ^ 4)]);
                a[mt][3] = __float_as_uint(As[rowAoff[mt] + 256 + (x0 ^ 4)]);
            }
            uint32_t b[4][2];
#pragma unroll
            for (int nt = 0; nt < 4; nt++) {
                b[nt][0] = rna_tf32_u(Bs[rowBoff[nt] + x0]);
                b[nt][1] = rna_tf32_u(Bs[rowBoff[nt] + (x0 ^ 4)]);
            }
#pragma unroll
            for (int mt = 0; mt < 4; mt++)
#pragma unroll
                for (int nt = 0; nt < 4; nt++)
                    MMA_TF32(acc[mt][nt], a[mt], b[nt]);
        }
    }

    // epilogue
#pragma unroll
    for (int mt = 0; mt < 4; mt++) {
        int m  = m0 + wm + mt * 16 + q;
        int m8 = m + 8;
        float w0 = 1.f, w1 = 1.f;
        if (use_wt) {
            w0 = (m  < n_e) ? d_wt[base + m]  : 0.f;
            w1 = (m8 < n_e) ? d_wt[base + m8] : 0.f;
        }
#pragma unroll
        for (int nt = 0; nt < 4; nt++) {
            int n = n0 + wn + nt * 8 + 2 * tig;
            if (m < n_e) {
                float2 v0 = make_float2(acc[mt][nt][0] * w0, acc[mt][nt][1] * w0);
                *(float2*)&C[(size_t)(base + m) * N + n] = v0;
            }
            if (m8 < n_e) {
                float2 v1 = make_float2(acc[mt][nt][2] * w1, acc[mt][nt][3] * w1);
                *(float2*)&C[(size_t)(base + m8) * N + n] = v1;
            }
        }
    }
}

// ---------------- 5. SiLU(g)*u elementwise (tf32-rounded) ----------------
__global__ void silu_kernel() {
    size_t i = (size_t)(blockIdx.x * blockDim.x + threadIdx.x) * 4;
    if (i >= (size_t)A_TOT * I_) return;
    float4 g = *(const float4*)&d_g[i];
    float4 u = *(const float4*)&d_u[i];
    float4 h;
    h.x = rna_tf32(g.x * (1.f / (1.f + __expf(-g.x))) * u.x);
    h.y = rna_tf32(g.y * (1.f / (1.f + __expf(-g.y))) * u.y);
    h.z = rna_tf32(g.z * (1.f / (1.f + __expf(-g.z))) * u.z);
    h.w = rna_tf32(g.w * (1.f / (1.f + __expf(-g.w))) * u.w);
    *(float4*)&d_hbuf[i] = h;
}

// ---------------- 6. Combine ----------------
__global__ void combine_kernel(float* __restrict__ out) {
    int gid = blockIdx.x * blockDim.x + threadIdx.x;
    int t = gid / (H_ / 4);
    int h4 = (gid - t * (H_ / 4)) * 4;
    float4 s = make_float4(0.f, 0.f, 0.f, 0.f);
#pragma unroll
    for (int k = 0; k < K_; k++) {
        int p = d_pos[t * K_ + k];
        float4 v = *(const float4*)&d_obuf[(size_t)p * H_ + h4];
        s.x += v.x; s.y += v.y; s.z += v.z; s.w += v.w;
    }
    *(float4*)&out[(size_t)t * H_ + h4] = s;
}

// ---------------- Host ----------------
extern "C" void kernel_launch(void* const* d_in, const int* in_sizes, int n_in,
                              void* d_out, int out_size) {
    const float* x      = (const float*)d_in[0];
    const float* logits = (const float*)d_in[1];
    const float* gate_w = (const float*)d_in[2];
    const float* up_w   = (const float*)d_in[3];
    const float* down_w = (const float*)d_in[4];
    float* out = (float*)d_out;

    static int smem_set = 0;
    if (!smem_set) {
        cudaFuncSetAttribute(gemm_tc, cudaFuncAttributeMaxDynamicSharedMemorySize, GEMM_SMEM);
        smem_set = 1;
    }

    float *xs_p, *g_p, *u_p, *h_p, *o_p;
    cudaGetSymbolAddress((void**)&xs_p, d_xs);
    cudaGetSymbolAddress((void**)&g_p,  d_g);
    cudaGetSymbolAddress((void**)&u_p,  d_u);
    cudaGetSymbolAddress((void**)&h_p,  d_hbuf);
    cudaGetSymbolAddress((void**)&o_p,  d_obuf);

    router_kernel<<<T_ / 256, 256>>>(logits);
    sort_kernel<<<1, 256>>>();
    gather_kernel<<<A_TOT, 256>>>(x);

    dim3 g1(I_ / BN, T_ / BM, E_);   // 11 x 16 x 16
    gemm_tc<<<g1, 256, GEMM_SMEM>>>(xs_p, gate_w, g_p, H_, I_, 0);
    gemm_tc<<<g1, 256, GEMM_SMEM>>>(xs_p, up_w,   u_p, H_, I_, 0);

    silu_kernel<<<(A_TOT * (size_t)I_ / 4 + 255) / 256, 256>>>();

    dim3 g2(H_ / BN, T_ / BM, E_);   // 16 x 16 x 16
    gemm_tc<<<g2, 256, GEMM_SMEM>>>(h_p, down_w, o_p, I_, H_, 1);

    combine_kernel<<<(T_ * H_ / 4) / 256, 256>>>(out);
}